// round 17
// baseline (speedup 1.0000x reference)
#include <cuda_runtime.h>
#include <cuda_fp16.h>
#include <cstdint>

#define SZ    4096
#define MTOT  8192
#define BM    128
#define BN    128
#define BK    64
#define KIT   (SZ / BK)          // 64 k-steps
#define NTHR  128                // 4 warps: 2m x 2n, warp tile 64x64
#define NSTG  3                  // cp.async stages (96KB -> 2 CTAs/SM)

// device scratch (no allocation allowed in kernel_launch)
__device__ __half g_Xh[(size_t)MTOT * SZ];   // x in fp16, row-major [M][K]
__device__ __half g_Gt[(size_t)SZ * SZ];     // Gt[n][k] = G[k][n], fp16, K-major

// ---------------------------------------------------------------------------
// helpers (base-PTX only: cp.async / ldmatrix / mma.sync)
// ---------------------------------------------------------------------------
__device__ __forceinline__ uint32_t smem_u32(const void* p) {
    uint32_t a;
    asm("{ .reg .u64 t; cvta.to.shared.u64 t, %1; cvt.u32.u64 %0, t; }"
        : "=r"(a) : "l"(p));
    return a;
}
__device__ __forceinline__ uint32_t swz128(uint32_t off) {
    return off ^ ((off >> 3) & 0x70);        // SW128: conflict-free 128B-row tiles
}
__device__ __forceinline__ void cp16(uint32_t sdst, const void* gsrc) {
    asm volatile("cp.async.cg.shared.global [%0], [%1], 16;" :: "r"(sdst), "l"(gsrc));
}
__device__ __forceinline__ void ldsm_x4(uint32_t& r0, uint32_t& r1, uint32_t& r2,
                                        uint32_t& r3, uint32_t addr) {
    asm volatile("ldmatrix.sync.aligned.m8n8.x4.shared.b16 {%0,%1,%2,%3}, [%4];"
                 : "=r"(r0), "=r"(r1), "=r"(r2), "=r"(r3) : "r"(addr));
}
__device__ __forceinline__ void mma16816(float* c, uint32_t a0, uint32_t a1,
                                         uint32_t a2, uint32_t a3,
                                         uint32_t b0, uint32_t b1) {
    asm volatile(
        "mma.sync.aligned.m16n8k16.row.col.f32.f16.f16.f32 "
        "{%0,%1,%2,%3}, {%4,%5,%6,%7}, {%8,%9}, {%0,%1,%2,%3};"
        : "+f"(c[0]), "+f"(c[1]), "+f"(c[2]), "+f"(c[3])
        : "r"(a0), "r"(a1), "r"(a2), "r"(a3), "r"(b0), "r"(b1));
}

// ---------------------------------------------------------------------------
// Kernel 1: x fp32 -> fp16. 2 float4 per thread -> one 16B store.
// ---------------------------------------------------------------------------
__global__ void k_convert_x(const float4* __restrict__ x) {
    size_t i = ((size_t)blockIdx.x * blockDim.x + threadIdx.x) * 2;  // float4 idx
    float4 v0 = x[i], v1 = x[i + 1];
    __half2 h0 = __floats2half2_rn(v0.x, v0.y);
    __half2 h1 = __floats2half2_rn(v0.z, v0.w);
    __half2 h2 = __floats2half2_rn(v1.x, v1.y);
    __half2 h3 = __floats2half2_rn(v1.z, v1.w);
    uint4 o;
    o.x = *reinterpret_cast<uint32_t*>(&h0);
    o.y = *reinterpret_cast<uint32_t*>(&h1);
    o.z = *reinterpret_cast<uint32_t*>(&h2);
    o.w = *reinterpret_cast<uint32_t*>(&h3);
    reinterpret_cast<uint4*>(g_Xh)[i >> 1] = o;
}

// ---------------------------------------------------------------------------
// Kernel 2: build Gt[n][k] = G[k][n] in fp16.
// ---------------------------------------------------------------------------
__global__ void __launch_bounds__(256)
k_build_gt(const float* __restrict__ core0, const float* __restrict__ core1,
           const float* __restrict__ core2) {
    const int x1 = blockIdx.y;
    const int k  = blockIdx.x * 256 + threadIdx.x;

    float c1r[64];  // C1[k, x1, c, b]
    const float4* c1p = reinterpret_cast<const float4*>(core1 + ((size_t)k * 16 + x1) * 64);
#pragma unroll
    for (int i = 0; i < 16; i++) {
        float4 v = c1p[i];
        c1r[4 * i] = v.x; c1r[4 * i + 1] = v.y; c1r[4 * i + 2] = v.z; c1r[4 * i + 3] = v.w;
    }
#pragma unroll
    for (int yc = 0; yc < 4; yc++) {
        float M[4][8];
#pragma unroll
        for (int yy = 0; yy < 4; yy++) {
            const int y = yc * 4 + yy;
            const float4* gp = reinterpret_cast<const float4*>(core0 + ((size_t)k * 16 + y) * 8);
            float4 a = gp[0], b = gp[1];
            float g0[8] = {a.x, a.y, a.z, a.w, b.x, b.y, b.z, b.w};
#pragma unroll
            for (int c = 0; c < 8; c++) {
                float s = 0.f;
#pragma unroll
                for (int bb = 0; bb < 8; bb++) s = fmaf(c1r[c * 8 + bb], g0[bb], s);
                M[yy][c] = s;
            }
        }
#pragma unroll
        for (int x2 = 0; x2 < 16; x2++) {
            const float4* cp = reinterpret_cast<const float4*>(core2 + ((size_t)k * 16 + x2) * 8);
            float4 a = cp[0], b = cp[1];
            float c2v[8] = {a.x, a.y, a.z, a.w, b.x, b.y, b.z, b.w};
#pragma unroll
            for (int yy = 0; yy < 4; yy++) {
                float s = 0.f;
#pragma unroll
                for (int c = 0; c < 8; c++) s = fmaf(c2v[c], M[yy][c], s);
                const int n = (yc * 4 + yy) * 256 + x1 * 16 + x2;
                g_Gt[(size_t)n * SZ + k] = __float2half_rn(s);
            }
        }
    }
}

// ---------------------------------------------------------------------------
// Kernel 3: GEMM out[m][n] = sum_k Xh[m][k] * Gt[n][k] + bias[n]
// R16 shell. CHANGE: cp.async packets shrunk to 2/thread and injected INSIDE
// each k16's MMA block (after mt=0-1 and after mt=2-3) — 8 packets/k-step,
// each fully absorbed by an MMA half-burst shadow. Commit-group structure
// (2 groups/k-step, wait_group 2) unchanged.
// ---------------------------------------------------------------------------
#define A_BYTES  (BM * BK * 2)                    // 16384 per stage
#define B_BYTES  (BN * BK * 2)                    // 16384 per stage
#define SM_A     0
#define SM_B     (NSTG * A_BYTES)                 // 49152
#define SM_BIAS  (SM_B + NSTG * B_BYTES)          // 98304
#define SM_TOTAL (SM_BIAS + BN * 4)               // 98816 (x2 CTAs = 193KB)

__global__ void __launch_bounds__(NTHR, 2)
k_gemm(const float* __restrict__ bias, float* __restrict__ out) {
    extern __shared__ char smem[];
    const uint32_t sb = smem_u32(smem);
    const int tid  = threadIdx.x;
    const int lane = tid & 31;
    const int wid  = tid >> 5;
    const int wm   = wid & 1;            // 2 m-warps x 64 rows
    const int wn   = wid >> 1;           // 2 n-warps x 64 cols
    const int m0 = blockIdx.y * BM;
    const int n0 = blockIdx.x * BN;

    float* sbias = reinterpret_cast<float*>(smem + SM_BIAS);
    sbias[tid] = bias[n0 + tid];

    // ---- loaders: eighth-stage packets (2 cp.async per thread each) ----
    const int chunk = tid & 7;           // 16B chunk within 128B row
    const int rbase = tid >> 3;          // 0..15
    // q = 0..3 selects rows [32q, 32q+32) of the 128-row operand tile
    auto load_A_q = [&](int ks, int stage, int q) {
        const uint32_t ab = sb + SM_A + stage * A_BYTES;
        const __half* ag = g_Xh + (size_t)(m0 + rbase + 32 * q) * SZ + ks * BK + chunk * 8;
#pragma unroll
        for (int it = 0; it < 2; it++) {
            const int r = rbase + 32 * q + 16 * it;
            cp16(ab + swz128((uint32_t)(r * 128 + chunk * 16)), ag + (size_t)(16 * it) * SZ);
        }
    };
    auto load_B_q = [&](int ks, int stage, int q) {
        const uint32_t bb = sb + SM_B + stage * B_BYTES;
        const __half* bg = g_Gt + (size_t)(n0 + rbase + 32 * q) * SZ + ks * BK + chunk * 8;
#pragma unroll
        for (int it = 0; it < 2; it++) {
            const int r = rbase + 32 * q + 16 * it;
            cp16(bb + swz128((uint32_t)(r * 128 + chunk * 16)), bg + (size_t)(16 * it) * SZ);
        }
    };
    auto commit = [&]() {
        asm volatile("cp.async.commit_group;" ::: "memory");
    };

    float acc[4][8][4];
#pragma unroll
    for (int mt = 0; mt < 4; mt++)
#pragma unroll
        for (int nt = 0; nt < 8; nt++)
#pragma unroll
            for (int j = 0; j < 4; j++) acc[mt][nt][j] = 0.f;

#pragma unroll
    for (int q = 0; q < 4; q++) load_A_q(0, 0, q);
    commit();
#pragma unroll
    for (int q = 0; q < 4; q++) load_B_q(0, 0, q);
    commit();
#pragma unroll
    for (int q = 0; q < 4; q++) load_A_q(1, 1, q);
    commit();
#pragma unroll
    for (int q = 0; q < 4; q++) load_B_q(1, 1, q);
    commit();

    // lane pieces for ldmatrix addressing
    const int g = lane >> 3;                                   // 0..3
    const int arow_off = ((lane >> 3) & 1) * 8 + (lane & 7);   // A row within 16
    const int acol_off = (lane >> 4) << 4;                     // A col byte (0/16)
    const int brow_off = ((g & 2) << 2) + (lane & 7);          // B row within 16
    const int bcol_off = (g & 1) << 4;                         // B col byte (0/16)

    // one k16 sub-step with two injected load payloads (p1 after mt=0-1,
    // p2 after mt=2-3). Frags scoped locally: no register growth.
    auto do_k16 = [&](uint32_t ab, uint32_t bb, int k16, auto p1, auto p2) {
        uint32_t a[4][4];
#pragma unroll
        for (int mt = 0; mt < 4; mt++) {
            const int row = wm * 64 + mt * 16 + arow_off;
            const int colb = k16 * 32 + acol_off;
            ldsm_x4(a[mt][0], a[mt][1], a[mt][2], a[mt][3],
                    ab + swz128((uint32_t)(row * 128 + colb)));
        }
        uint32_t b[8][2];
#pragma unroll
        for (int np = 0; np < 4; np++) {
            const int row = wn * 64 + np * 16 + brow_off;
            const int colb = k16 * 32 + bcol_off;
            uint32_t r0, r1, r2, r3;
            ldsm_x4(r0, r1, r2, r3, bb + swz128((uint32_t)(row * 128 + colb)));
            b[2 * np][0] = r0; b[2 * np][1] = r1;
            b[2 * np + 1][0] = r2; b[2 * np + 1][1] = r3;
        }
#pragma unroll
        for (int mt = 0; mt < 2; mt++)
#pragma unroll
            for (int nt = 0; nt < 8; nt++)
                mma16816(acc[mt][nt], a[mt][0], a[mt][1], a[mt][2], a[mt][3],
                         b[nt][0], b[nt][1]);
        p1();
#pragma unroll
        for (int mt = 2; mt < 4; mt++)
#pragma unroll
            for (int nt = 0; nt < 8; nt++)
                mma16816(acc[mt][nt], a[mt][0], a[mt][1], a[mt][2], a[mt][3],
                         b[nt][0], b[nt][1]);
        p2();
    };

    for (int ks = 0; ks < KIT; ks++) {
        asm volatile("cp.async.wait_group 2;" ::: "memory");
        __syncthreads();

        const uint32_t ab = sb + SM_A + (ks % NSTG) * A_BYTES;
        const uint32_t bb = sb + SM_B + (ks % NSTG) * B_BYTES;
        const bool pf = (ks + 2 < KIT);
        const int st = (ks + 2) % NSTG;
        const int k2 = ks + 2;

        do_k16(ab, bb, 0, [&]{ if (pf) load_A_q(k2, st, 0); },
                          [&]{ if (pf) load_A_q(k2, st, 1); });
        do_k16(ab, bb, 1, [&]{ if (pf) load_A_q(k2, st, 2); },
                          [&]{ if (pf) load_A_q(k2, st, 3); commit(); });
        do_k16(ab, bb, 2, [&]{ if (pf) load_B_q(k2, st, 0); },
                          [&]{ if (pf) load_B_q(k2, st, 1); });
        do_k16(ab, bb, 3, [&]{ if (pf) load_B_q(k2, st, 2); },
                          [&]{ if (pf) load_B_q(k2, st, 3); commit(); });
    }

    // ---- epilogue ----
    const int crow = lane >> 2;
    const int ccol = (lane & 3) * 2;
#pragma unroll
    for (int mt = 0; mt < 4; mt++) {
        const int m = m0 + wm * 64 + mt * 16 + crow;
#pragma unroll
        for (int nt = 0; nt < 8; nt++) {
            const int nc = wn * 64 + nt * 8 + ccol;
            float2 v0, v1;
            v0.x = acc[mt][nt][0] + sbias[nc];
            v0.y = acc[mt][nt][1] + sbias[nc + 1];
            v1.x = acc[mt][nt][2] + sbias[nc];
            v1.y = acc[mt][nt][3] + sbias[nc + 1];
            *reinterpret_cast<float2*>(out + (size_t)m * SZ + n0 + nc)       = v0;
            *reinterpret_cast<float2*>(out + (size_t)(m + 8) * SZ + n0 + nc) = v1;
        }
    }
}

// ---------------------------------------------------------------------------
extern "C" void kernel_launch(void* const* d_in, const int* in_sizes, int n_in,
                              void* d_out, int out_size) {
    const float* x     = (const float*)d_in[0];
    const float* core0 = (const float*)d_in[1];
    const float* core1 = (const float*)d_in[2];
    const float* core2 = (const float*)d_in[3];
    const float* bias  = (const float*)d_in[4];
    float* out = (float*)d_out;

    static bool attr_set = false;
    if (!attr_set) {
        cudaFuncSetAttribute(k_gemm, cudaFuncAttributeMaxDynamicSharedMemorySize, SM_TOTAL);
        attr_set = true;
    }

    k_convert_x<<<(int)((size_t)MTOT * SZ / 8 / 256), 256>>>(
        reinterpret_cast<const float4*>(x));
    k_build_gt<<<dim3(16, 16), 256>>>(core0, core1, core2);
    k_gemm<<<dim3(SZ / BN, MTOT / BM), NTHR, SM_TOTAL>>>(bias, out);
}